// round 14
// baseline (speedup 1.0000x reference)
#include <cuda_runtime.h>
#include <cuda_fp16.h>
#include <cstdint>
#include <math.h>

// Problem constants
#define T_TOK 4096
#define D_MODEL 1024
#define D_MLP 3584
#define NEXP 8
#define EHALF 4

// GEMM tile config
#define BM 128
#define BN 64
#define BK 64
#define THREADS 256
#define NS1 4            // gemm1 pipeline stages (1 CTA/SM -> 128KB smem OK)
#define NS2 4            // gemm2 pipeline stages

// smem stage sizes (bytes)
#define A_BYTES (BM * BK * 2)             // 16384
#define B_BYTES (BN * BK * 2)             // 8192
#define STAGE1 (A_BYTES + 2 * B_BYTES)    // 32768 (gemm1: A + B1 + B3)
#define STAGE2 (A_BYTES + B_BYTES)        // 24576 (gemm2: A + B)

// ---------------- device scratch (static: no cudaMalloc allowed) ----------------
static __device__ __align__(16) __half g_xh[T_TOK * D_MODEL];
static __device__ __align__(16) __half g_w1h[NEXP * D_MLP * D_MODEL];
static __device__ __align__(16) __half g_w3h[NEXP * D_MLP * D_MODEL];
static __device__ __align__(16) __half g_w2h[NEXP * D_MODEL * D_MLP];
static __device__ __align__(16) __half g_h[(size_t)NEXP * T_TOK * D_MLP];
static __device__ int    g_cnt[NEXP];
static __device__ int    g_list[NEXP * T_TOK];
static __device__ float  g_wts[NEXP * T_TOK];

// ---------------- helpers ----------------
__device__ __forceinline__ void mma16816(float* c, const uint32_t* a, const uint32_t* b) {
    asm volatile(
        "mma.sync.aligned.m16n8k16.row.col.f32.f16.f16.f32 "
        "{%0,%1,%2,%3}, {%4,%5,%6,%7}, {%8,%9}, {%0,%1,%2,%3};"
        : "+f"(c[0]), "+f"(c[1]), "+f"(c[2]), "+f"(c[3])
        : "r"(a[0]), "r"(a[1]), "r"(a[2]), "r"(a[3]), "r"(b[0]), "r"(b[1]));
}

__device__ __forceinline__ void ldsm4(uint32_t* r, uint32_t saddr) {
    asm volatile("ldmatrix.sync.aligned.m8n8.x4.shared.b16 {%0,%1,%2,%3}, [%4];"
                 : "=r"(r[0]), "=r"(r[1]), "=r"(r[2]), "=r"(r[3]) : "r"(saddr));
}

__device__ __forceinline__ void cp16(uint32_t dst, const void* src) {
    asm volatile("cp.async.cg.shared.global [%0], [%1], 16;" :: "r"(dst), "l"(src));
}
#define CP_COMMIT() asm volatile("cp.async.commit_group;")
#define CP_WAIT2()  asm volatile("cp.async.wait_group 2;")
#define CP_WAIT1()  asm volatile("cp.async.wait_group 1;")
#define CP_WAIT0()  asm volatile("cp.async.wait_group 0;")

__device__ __forceinline__ uint32_t smem_u32(const void* p) {
    return (uint32_t)__cvta_generic_to_shared(p);
}

// ---------------- kernel 0: zero output + counters ----------------
__global__ void zero_kernel(float4* out4, int n4) {
    int i = blockIdx.x * blockDim.x + threadIdx.x;
    float4 z = make_float4(0.f, 0.f, 0.f, 0.f);
    for (; i < n4; i += gridDim.x * blockDim.x) out4[i] = z;
    if (blockIdx.x == 0 && threadIdx.x < NEXP) g_cnt[threadIdx.x] = 0;
}

// ---------------- W1/W3 fp32 -> fp16, per-expert-half chunks ----------------
__global__ void cvt_w13_kernel(const float* __restrict__ w1,
                               const float* __restrict__ w3, int ebase) {
    const int n4 = (EHALF * D_MLP * D_MODEL) / 4;
    const size_t base4 = (size_t)ebase * (D_MLP * D_MODEL / 4);
    const float* src = (blockIdx.y == 0) ? w1 : w3;
    __half* dst = (blockIdx.y == 0) ? g_w1h : g_w3h;
    const float4* s4 = reinterpret_cast<const float4*>(src) + base4;
    __half2* d2 = reinterpret_cast<__half2*>(dst) + 2 * base4;
    int i = blockIdx.x * blockDim.x + threadIdx.x;
    for (; i < n4; i += gridDim.x * blockDim.x) {
        float4 v = s4[i];
        d2[2 * i + 0] = __floats2half2_rn(v.x, v.y);
        d2[2 * i + 1] = __floats2half2_rn(v.z, v.w);
    }
}

__global__ void cvt_w2_kernel(const float* __restrict__ w2) {
    const int n4 = (NEXP * D_MLP * D_MODEL) / 4;
    const float4* s4 = reinterpret_cast<const float4*>(w2);
    __half2* d2 = reinterpret_cast<__half2*>(g_w2h);
    int i = blockIdx.x * blockDim.x + threadIdx.x;
    for (; i < n4; i += gridDim.x * blockDim.x) {
        float4 v = s4[i];
        d2[2 * i + 0] = __floats2half2_rn(v.x, v.y);
        d2[2 * i + 1] = __floats2half2_rn(v.z, v.w);
    }
}

// ---------------- gating (warp per token) + x->fp16 ----------------
__global__ void gate_kernel(const float* __restrict__ x, const float* __restrict__ wg) {
    int t = blockIdx.x * 4 + (threadIdx.x >> 5);
    int lane = threadIdx.x & 31;
    if (t >= T_TOK) return;
    const float* xr = x + (size_t)t * D_MODEL;
    float acc[NEXP];
#pragma unroll
    for (int e = 0; e < NEXP; e++) acc[e] = 0.f;
    for (int d = lane; d < D_MODEL; d += 32) {
        float xv = xr[d];
        g_xh[(size_t)t * D_MODEL + d] = __float2half_rn(xv);
#pragma unroll
        for (int e = 0; e < NEXP; e++) acc[e] += xv * wg[e * D_MODEL + d];
    }
#pragma unroll
    for (int e = 0; e < NEXP; e++)
#pragma unroll
        for (int o = 16; o; o >>= 1) acc[e] += __shfl_xor_sync(0xFFFFFFFFu, acc[e], o);
    if (lane == 0) {
        int i0 = 0;
        float l0 = acc[0];
#pragma unroll
        for (int e = 1; e < NEXP; e++)
            if (acc[e] > l0) { l0 = acc[e]; i0 = e; }
        int i1 = -1;
        float l1 = -INFINITY;
#pragma unroll
        for (int e = 0; e < NEXP; e++)
            if (e != i0 && acc[e] > l1) { l1 = acc[e]; i1 = e; }
        float e1 = expf(l1 - l0);
        float s = 1.f + e1;
        float w0 = 1.f / s, w1 = e1 / s;
        int p0 = atomicAdd(&g_cnt[i0], 1);
        g_list[i0 * T_TOK + p0] = t;
        g_wts[i0 * T_TOK + p0] = w0;
        int p1 = atomicAdd(&g_cnt[i1], 1);
        g_list[i1 * T_TOK + p1] = t;
        g_wts[i1 * T_TOK + p1] = w1;
    }
}

// ---------------- grouped GEMM1: h = silu(X@W1^T) * (X@W3^T), fp16 out ----------------
// grid: (D_MLP/BN, T_TOK/BM, EHALF), block 256, dynamic smem NS1*STAGE1
__global__ void __launch_bounds__(THREADS, 1) gemm1_kernel(int ebase) {
    int e = blockIdx.z + ebase, mt = blockIdx.y, nt = blockIdx.x;
    int cnt = g_cnt[e];
    if (mt * BM >= cnt) return;

    extern __shared__ __align__(128) char sm1[];
    uint32_t sbase = smem_u32(sm1);

    int tid = threadIdx.x, lane = tid & 31, warp = tid >> 5;
    int wm = warp & 3, wn = warp >> 2;       // 4 x 2 warp grid
    int g = lane >> 2, tg = lane & 3;
    int l15 = lane & 15, hi = lane >> 4;

    const __half* asrc[4]; uint32_t adst[4];
#pragma unroll
    for (int i = 0; i < 4; i++) {
        int lin = i * THREADS + tid;
        int row = lin >> 3, ch = lin & 7;
        int s = mt * BM + row;
        int tok = g_list[e * T_TOK + min(s, cnt - 1)];
        asrc[i] = g_xh + (size_t)tok * D_MODEL + ch * 8;
        adst[i] = sbase + row * 128 + ((uint32_t)(ch ^ (row & 7)) << 4);
    }
    const __half* b1src[2]; const __half* b3src[2]; uint32_t bdst[2];
#pragma unroll
    for (int i = 0; i < 2; i++) {
        int lin = i * THREADS + tid;
        int row = lin >> 3, ch = lin & 7;
        size_t off = ((size_t)e * D_MLP + nt * BN + row) * D_MODEL + ch * 8;
        b1src[i] = g_w1h + off;
        b3src[i] = g_w3h + off;
        bdst[i] = sbase + A_BYTES + row * 128 + ((uint32_t)(ch ^ (row & 7)) << 4);
    }

    uint32_t aA[2], mA[2];
#pragma unroll
    for (int tm = 0; tm < 2; tm++) {
        int r = wm * 32 + tm * 16 + l15;
        aA[tm] = sbase + r * 128;
        mA[tm] = (uint32_t)((hi ^ (r & 7)) << 4);
    }
    uint32_t aB[2], mB[2];
#pragma unroll
    for (int ns = 0; ns < 2; ns++) {
        int r = wn * 32 + ns * 16 + l15;
        aB[ns] = sbase + A_BYTES + r * 128;
        mB[ns] = (uint32_t)((hi ^ (r & 7)) << 4);
    }

    float c1[2][4][4] = {}, c3[2][4][4] = {};

    const int NK = D_MODEL / BK;  // 16

    auto fill = [&](int st) {
        uint32_t so = (uint32_t)st * STAGE1;
#pragma unroll
        for (int i = 0; i < 4; i++) { cp16(adst[i] + so, asrc[i]); asrc[i] += BK; }
#pragma unroll
        for (int i = 0; i < 2; i++) {
            cp16(bdst[i] + so, b1src[i]);
            cp16(bdst[i] + so + B_BYTES, b3src[i]);
            b1src[i] += BK;
            b3src[i] += BK;
        }
        CP_COMMIT();
    };

    fill(0);
    fill(1);
    fill(2);

    // double-buffered fragments
    uint32_t a[2][2][4], q1[2][2][4], q3[2][2][4];

    for (int kt = 0; kt < NK; kt++) {
        int rem = NK - 1 - kt;
        if (rem >= 2)      { CP_WAIT2(); }
        else if (rem == 1) { CP_WAIT1(); }
        else               { CP_WAIT0(); }
        __syncthreads();
        if (kt + 3 < NK) fill((kt + 3) & 3);
        uint32_t so = (uint32_t)(kt & 3) * STAGE1;
        uint32_t aAso0 = aA[0] + so, aAso1 = aA[1] + so;
        uint32_t aBso0 = aB[0] + so, aBso1 = aB[1] + so;

        auto ldfrag = [&](int buf, int kk) {
            uint32_t kk32 = (uint32_t)kk << 5;
            ldsm4(a[buf][0], aAso0 + (kk32 ^ mA[0]));
            ldsm4(a[buf][1], aAso1 + (kk32 ^ mA[1]));
            uint32_t ad0 = aBso0 + (kk32 ^ mB[0]);
            uint32_t ad1 = aBso1 + (kk32 ^ mB[1]);
            ldsm4(q1[buf][0], ad0);
            ldsm4(q1[buf][1], ad1);
            ldsm4(q3[buf][0], ad0 + B_BYTES);
            ldsm4(q3[buf][1], ad1 + B_BYTES);
        };

        ldfrag(0, 0);
#pragma unroll
        for (int kk = 0; kk < 4; kk++) {
            int cur = kk & 1;
            if (kk < 3) ldfrag(cur ^ 1, kk + 1);
#pragma unroll
            for (int tm = 0; tm < 2; tm++)
#pragma unroll
                for (int ns = 0; ns < 2; ns++) {
                    uint32_t b1a[2] = {q1[cur][ns][0], q1[cur][ns][2]};
                    uint32_t b1b[2] = {q1[cur][ns][1], q1[cur][ns][3]};
                    uint32_t b3a[2] = {q3[cur][ns][0], q3[cur][ns][2]};
                    uint32_t b3b[2] = {q3[cur][ns][1], q3[cur][ns][3]};
                    mma16816(c1[tm][ns * 2 + 0], a[cur][tm], b1a);
                    mma16816(c1[tm][ns * 2 + 1], a[cur][tm], b1b);
                    mma16816(c3[tm][ns * 2 + 0], a[cur][tm], b3a);
                    mma16816(c3[tm][ns * 2 + 1], a[cur][tm], b3b);
                }
        }
    }

    // epilogue: h = silu(h1) * h3 -> fp16
#pragma unroll
    for (int tm = 0; tm < 2; tm++)
#pragma unroll
        for (int pair = 0; pair < 2; pair++) {
            int s = mt * BM + wm * 32 + tm * 16 + g + pair * 8;
            if (s >= cnt) continue;
#pragma unroll
            for (int tn = 0; tn < 4; tn++) {
                float h1a = c1[tm][tn][pair * 2 + 0];
                float h1b = c1[tm][tn][pair * 2 + 1];
                float h3a = c3[tm][tn][pair * 2 + 0];
                float h3b = c3[tm][tn][pair * 2 + 1];
                float ha = h1a / (1.f + expf(-h1a)) * h3a;
                float hb = h1b / (1.f + expf(-h1b)) * h3b;
                int col = nt * BN + wn * 32 + tn * 8 + tg * 2;
                *reinterpret_cast<__half2*>(&g_h[((size_t)e * T_TOK + s) * D_MLP + col]) =
                    __floats2half2_rn(ha, hb);
            }
        }
}

// ---------------- grouped GEMM2: out += w * (H @ W2^T), fused atomic combine ----------------
// grid: (D_MODEL/BN, T_TOK/BM, EHALF), block 256, dynamic smem NS2*STAGE2
__global__ void __launch_bounds__(THREADS, 1) gemm2_kernel(float* __restrict__ out, int ebase) {
    int e = blockIdx.z + ebase, mt = blockIdx.y, nt = blockIdx.x;
    int cnt = g_cnt[e];
    if (mt * BM >= cnt) return;

    extern __shared__ __align__(128) char sm2[];
    uint32_t sbase = smem_u32(sm2);

    int tid = threadIdx.x, lane = tid & 31, warp = tid >> 5;
    int wm = warp & 3, wn = warp >> 2;
    int g = lane >> 2, tg = lane & 3;
    int l15 = lane & 15, hi = lane >> 4;

    const __half* asrc[4]; uint32_t adst[4];
#pragma unroll
    for (int i = 0; i < 4; i++) {
        int lin = i * THREADS + tid;
        int row = lin >> 3, ch = lin & 7;
        asrc[i] = g_h + ((size_t)e * T_TOK + mt * BM + row) * D_MLP + ch * 8;
        adst[i] = sbase + row * 128 + ((uint32_t)(ch ^ (row & 7)) << 4);
    }
    const __half* bsrc[2]; uint32_t bdst[2];
#pragma unroll
    for (int i = 0; i < 2; i++) {
        int lin = i * THREADS + tid;
        int row = lin >> 3, ch = lin & 7;
        bsrc[i] = g_w2h + ((size_t)e * D_MODEL + nt * BN + row) * D_MLP + ch * 8;
        bdst[i] = sbase + A_BYTES + row * 128 + ((uint32_t)(ch ^ (row & 7)) << 4);
    }

    uint32_t aA[2], mA[2];
#pragma unroll
    for (int tm = 0; tm < 2; tm++) {
        int r = wm * 32 + tm * 16 + l15;
        aA[tm] = sbase + r * 128;
        mA[tm] = (uint32_t)((hi ^ (r & 7)) << 4);
    }
    uint32_t aB[2], mB[2];
#pragma unroll
    for (int ns = 0; ns < 2; ns++) {
        int r = wn * 32 + ns * 16 + l15;
        aB[ns] = sbase + A_BYTES + r * 128;
        mB[ns] = (uint32_t)((hi ^ (r & 7)) << 4);
    }

    float c[2][4][4] = {};

    const int NK = D_MLP / BK;  // 56

    auto fill = [&](int st) {
        uint32_t so = (uint32_t)st * STAGE2;
#pragma unroll
        for (int i = 0; i < 4; i++) { cp16(adst[i] + so, asrc[i]); asrc[i] += BK; }
#pragma unroll
        for (int i = 0; i < 2; i++) { cp16(bdst[i] + so, bsrc[i]); bsrc[i] += BK; }
        CP_COMMIT();
    };

    fill(0);
    fill(1);
    fill(2);

    uint32_t a[2][2][4], q[2][2][4];

    for (int kt = 0; kt < NK; kt++) {
        int rem = NK - 1 - kt;
        if (rem >= 2)      { CP_WAIT2(); }
        else if (rem == 1) { CP_WAIT1(); }
        else               { CP_WAIT0(); }
        __syncthreads();
        if (kt + 3 < NK) fill((kt + 3) & 3);
        uint32_t so = (uint32_t)(kt & 3) * STAGE2;
        uint32_t aAso0 = aA[0] + so, aAso1 = aA[1] + so;
        uint32_t aBso0 = aB[0] + so, aBso1 = aB[1] + so;

        auto ldfrag = [&](int buf, int kk) {
            uint32_t kk32 = (uint32_t)kk << 5;
            ldsm4(a[buf][0], aAso0 + (kk32 ^ mA[0]));
            ldsm4(a[buf][1], aAso1 + (kk32 ^ mA[1]));
            ldsm4(q[buf][0], aBso0 + (kk32 ^ mB[0]));
            ldsm4(q[buf][1], aBso1 + (kk32 ^ mB[1]));
        };

        ldfrag(0, 0);
#pragma unroll
        for (int kk = 0; kk < 4; kk++) {
            int cur = kk & 1;
            if (kk < 3) ldfrag(cur ^ 1, kk + 1);
#pragma unroll
            for (int tm = 0; tm < 2; tm++)
#pragma unroll
                for (int ns = 0; ns < 2; ns++) {
                    uint32_t ba[2] = {q[cur][ns][0], q[cur][ns][2]};
                    uint32_t bb[2] = {q[cur][ns][1], q[cur][ns][3]};
                    mma16816(c[tm][ns * 2 + 0], a[cur][tm], ba);
                    mma16816(c[tm][ns * 2 + 1], a[cur][tm], bb);
                }
        }
    }

    // epilogue: weighted atomic combine directly into output
#pragma unroll
    for (int tm = 0; tm < 2; tm++)
#pragma unroll
        for (int pair = 0; pair < 2; pair++) {
            int s = mt * BM + wm * 32 + tm * 16 + g + pair * 8;
            if (s >= cnt) continue;
            int token = g_list[e * T_TOK + s];
            float w = g_wts[e * T_TOK + s];
            float* dst = out + (size_t)token * D_MODEL;
#pragma unroll
            for (int tn = 0; tn < 4; tn++) {
                int col = nt * BN + wn * 32 + tn * 8 + tg * 2;
                atomicAdd(dst + col + 0, c[tm][tn][pair * 2 + 0] * w);
                atomicAdd(dst + col + 1, c[tm][tn][pair * 2 + 1] * w);
            }
        }
}

// ---------------- stream/event resources (host objects, created once pre-capture) ----------------
struct MoeResources {
    cudaStream_t s1, s2;
    cudaEvent_t e0, eg, ecA, ecB, eg1a, e2a;
    MoeResources() {
        cudaStreamCreateWithFlags(&s1, cudaStreamNonBlocking);
        cudaStreamCreateWithFlags(&s2, cudaStreamNonBlocking);
        cudaEventCreateWithFlags(&e0, cudaEventDisableTiming);
        cudaEventCreateWithFlags(&eg, cudaEventDisableTiming);
        cudaEventCreateWithFlags(&ecA, cudaEventDisableTiming);
        cudaEventCreateWithFlags(&ecB, cudaEventDisableTiming);
        cudaEventCreateWithFlags(&eg1a, cudaEventDisableTiming);
        cudaEventCreateWithFlags(&e2a, cudaEventDisableTiming);
        cudaFuncSetAttribute(gemm1_kernel, cudaFuncAttributeMaxDynamicSharedMemorySize, NS1 * STAGE1);
        cudaFuncSetAttribute(gemm2_kernel, cudaFuncAttributeMaxDynamicSharedMemorySize, NS2 * STAGE2);
    }
};

// ---------------- launch ----------------
extern "C" void kernel_launch(void* const* d_in, const int* in_sizes, int n_in,
                              void* d_out, int out_size) {
    const float* x = (const float*)d_in[0];
    const float* w_gate = (const float*)d_in[1];
    const float* w1 = (const float*)d_in[2];
    const float* w3 = (const float*)d_in[3];
    const float* w2 = (const float*)d_in[4];
    float* out = (float*)d_out;

    static MoeResources res;  // constructed on first (non-captured) call

    // fork point on the main (captured) stream
    cudaEventRecord(res.e0, 0);

    // s1: zero output + counters -> gating (+ x fp16 conversion)
    cudaStreamWaitEvent(res.s1, res.e0, 0);
    zero_kernel<<<1024, 256, 0, res.s1>>>((float4*)out, (T_TOK * D_MODEL) / 4);
    gate_kernel<<<T_TOK / 4, 128, 0, res.s1>>>(x, w_gate);
    cudaEventRecord(res.eg, res.s1);

    // main: convert W1/W3 for experts 0-3 only (the gemm1a critical path)
    dim3 gcvt(1024, 2);
    cvt_w13_kernel<<<gcvt, 256>>>(w1, w3, 0);
    cudaEventRecord(res.ecA, 0);

    // s2: convert W1/W3 experts 4-7 (concurrent with gemm1a), then W2
    cudaStreamWaitEvent(res.s2, res.ecA, 0);
    cvt_w13_kernel<<<gcvt, 256, 0, res.s2>>>(w1, w3, EHALF);
    cudaEventRecord(res.ecB, res.s2);
    cvt_w2_kernel<<<2048, 256, 0, res.s2>>>(w2);

    // main: gemm1a (experts 0-3) after gate; weights e0-3 ready via stream order
    cudaStreamWaitEvent(0, res.eg, 0);
    dim3 g1(D_MLP / BN, T_TOK / BM, EHALF);
    gemm1_kernel<<<g1, THREADS, NS1 * STAGE1>>>(0);
    cudaEventRecord(res.eg1a, 0);

    // s2: gemm2a (experts 0-3) — waits gemm1a (event) + W2 cvt (stream order);
    // runs concurrent with gemm1b, filling its tail waves
    cudaStreamWaitEvent(res.s2, res.eg1a, 0);
    dim3 g2(D_MODEL / BN, T_TOK / BM, EHALF);
    gemm2_kernel<<<g2, THREADS, NS2 * STAGE2, res.s2>>>(out, 0);
    cudaEventRecord(res.e2a, res.s2);

    // main: gemm1b (experts 4-7) after its weight chunk
    cudaStreamWaitEvent(0, res.ecB, 0);
    gemm1_kernel<<<g1, THREADS, NS1 * STAGE1>>>(EHALF);

    // main: gemm2b (experts 4-7) after gemm1b (stream order) + gemm2a branch join
    cudaStreamWaitEvent(0, res.e2a, 0);
    gemm2_kernel<<<g2, THREADS, NS2 * STAGE2>>>(out, EHALF);
}

// round 15
// speedup vs baseline: 1.1705x; 1.1705x over previous
#include <cuda_runtime.h>
#include <cuda_fp16.h>
#include <cstdint>
#include <math.h>

// Problem constants
#define T_TOK 4096
#define D_MODEL 1024
#define D_MLP 3584
#define NEXP 8
#define EHALF 4
#define EQTR 2

// GEMM tile config
#define BM 128
#define BN 64
#define BK 64
#define THREADS 256
#define NS1 3            // gemm1 pipeline stages
#define NS2 4            // gemm2 pipeline stages

// smem stage sizes (bytes)
#define A_BYTES (BM * BK * 2)             // 16384
#define B_BYTES (BN * BK * 2)             // 8192
#define STAGE1 (A_BYTES + 2 * B_BYTES)    // 32768 (gemm1: A + B1 + B3)
#define STAGE2 (A_BYTES + B_BYTES)        // 24576 (gemm2: A + B)

// ---------------- device scratch (static: no cudaMalloc allowed) ----------------
static __device__ __align__(16) __half g_xh[T_TOK * D_MODEL];
static __device__ __align__(16) __half g_w1h[NEXP * D_MLP * D_MODEL];
static __device__ __align__(16) __half g_w3h[NEXP * D_MLP * D_MODEL];
static __device__ __align__(16) __half g_w2h[NEXP * D_MODEL * D_MLP];
static __device__ __align__(16) __half g_h[(size_t)NEXP * T_TOK * D_MLP];
static __device__ int    g_cnt[NEXP];
static __device__ int    g_list[NEXP * T_TOK];
static __device__ float  g_wts[NEXP * T_TOK];

// ---------------- helpers ----------------
__device__ __forceinline__ void mma16816(float* c, const uint32_t* a, const uint32_t* b) {
    asm volatile(
        "mma.sync.aligned.m16n8k16.row.col.f32.f16.f16.f32 "
        "{%0,%1,%2,%3}, {%4,%5,%6,%7}, {%8,%9}, {%0,%1,%2,%3};"
        : "+f"(c[0]), "+f"(c[1]), "+f"(c[2]), "+f"(c[3])
        : "r"(a[0]), "r"(a[1]), "r"(a[2]), "r"(a[3]), "r"(b[0]), "r"(b[1]));
}

__device__ __forceinline__ void ldsm4(uint32_t* r, uint32_t saddr) {
    asm volatile("ldmatrix.sync.aligned.m8n8.x4.shared.b16 {%0,%1,%2,%3}, [%4];"
                 : "=r"(r[0]), "=r"(r[1]), "=r"(r[2]), "=r"(r[3]) : "r"(saddr));
}

__device__ __forceinline__ void cp16(uint32_t dst, const void* src) {
    asm volatile("cp.async.cg.shared.global [%0], [%1], 16;" :: "r"(dst), "l"(src));
}
#define CP_COMMIT() asm volatile("cp.async.commit_group;")
#define CP_WAIT2()  asm volatile("cp.async.wait_group 2;")
#define CP_WAIT1()  asm volatile("cp.async.wait_group 1;")
#define CP_WAIT0()  asm volatile("cp.async.wait_group 0;")

__device__ __forceinline__ uint32_t smem_u32(const void* p) {
    return (uint32_t)__cvta_generic_to_shared(p);
}

// ---------------- kernel 0: zero output + counters ----------------
__global__ void zero_kernel(float4* out4, int n4) {
    int i = blockIdx.x * blockDim.x + threadIdx.x;
    float4 z = make_float4(0.f, 0.f, 0.f, 0.f);
    for (; i < n4; i += gridDim.x * blockDim.x) out4[i] = z;
    if (blockIdx.x == 0 && threadIdx.x < NEXP) g_cnt[threadIdx.x] = 0;
}

// ---------------- W1/W3 fp32 -> fp16, per-expert-chunk ----------------
// grid: (gx, 2); blockIdx.y: 0 -> W1, 1 -> W3.
__global__ void cvt_w13_kernel(const float* __restrict__ w1,
                               const float* __restrict__ w3, int ebase, int ecount) {
    const int n4 = ecount * (D_MLP * D_MODEL / 4);
    const size_t base4 = (size_t)ebase * (D_MLP * D_MODEL / 4);
    const float* src = (blockIdx.y == 0) ? w1 : w3;
    __half* dst = (blockIdx.y == 0) ? g_w1h : g_w3h;
    const float4* s4 = reinterpret_cast<const float4*>(src) + base4;
    __half2* d2 = reinterpret_cast<__half2*>(dst) + 2 * base4;
    int i = blockIdx.x * blockDim.x + threadIdx.x;
    for (; i < n4; i += gridDim.x * blockDim.x) {
        float4 v = s4[i];
        d2[2 * i + 0] = __floats2half2_rn(v.x, v.y);
        d2[2 * i + 1] = __floats2half2_rn(v.z, v.w);
    }
}

__global__ void cvt_w2_kernel(const float* __restrict__ w2) {
    const int n4 = (NEXP * D_MLP * D_MODEL) / 4;
    const float4* s4 = reinterpret_cast<const float4*>(w2);
    __half2* d2 = reinterpret_cast<__half2*>(g_w2h);
    int i = blockIdx.x * blockDim.x + threadIdx.x;
    for (; i < n4; i += gridDim.x * blockDim.x) {
        float4 v = s4[i];
        d2[2 * i + 0] = __floats2half2_rn(v.x, v.y);
        d2[2 * i + 1] = __floats2half2_rn(v.z, v.w);
    }
}

// ---------------- gating (warp per token) + x->fp16 ----------------
__global__ void gate_kernel(const float* __restrict__ x, const float* __restrict__ wg) {
    int t = blockIdx.x * 4 + (threadIdx.x >> 5);
    int lane = threadIdx.x & 31;
    if (t >= T_TOK) return;
    const float* xr = x + (size_t)t * D_MODEL;
    float acc[NEXP];
#pragma unroll
    for (int e = 0; e < NEXP; e++) acc[e] = 0.f;
    for (int d = lane; d < D_MODEL; d += 32) {
        float xv = xr[d];
        g_xh[(size_t)t * D_MODEL + d] = __float2half_rn(xv);
#pragma unroll
        for (int e = 0; e < NEXP; e++) acc[e] += xv * wg[e * D_MODEL + d];
    }
#pragma unroll
    for (int e = 0; e < NEXP; e++)
#pragma unroll
        for (int o = 16; o; o >>= 1) acc[e] += __shfl_xor_sync(0xFFFFFFFFu, acc[e], o);
    if (lane == 0) {
        int i0 = 0;
        float l0 = acc[0];
#pragma unroll
        for (int e = 1; e < NEXP; e++)
            if (acc[e] > l0) { l0 = acc[e]; i0 = e; }
        int i1 = -1;
        float l1 = -INFINITY;
#pragma unroll
        for (int e = 0; e < NEXP; e++)
            if (e != i0 && acc[e] > l1) { l1 = acc[e]; i1 = e; }
        float e1 = expf(l1 - l0);
        float s = 1.f + e1;
        float w0 = 1.f / s, w1 = e1 / s;
        int p0 = atomicAdd(&g_cnt[i0], 1);
        g_list[i0 * T_TOK + p0] = t;
        g_wts[i0 * T_TOK + p0] = w0;
        int p1 = atomicAdd(&g_cnt[i1], 1);
        g_list[i1 * T_TOK + p1] = t;
        g_wts[i1 * T_TOK + p1] = w1;
    }
}

// ---------------- grouped GEMM1: h = silu(X@W1^T) * (X@W3^T), fp16 out ----------------
// grid: (D_MLP/BN, T_TOK/BM, nexperts), block 256, dynamic smem NS1*STAGE1
__global__ void __launch_bounds__(THREADS, 2) gemm1_kernel(int ebase) {
    int e = blockIdx.z + ebase, mt = blockIdx.y, nt = blockIdx.x;
    int cnt = g_cnt[e];
    if (mt * BM >= cnt) return;

    extern __shared__ __align__(128) char sm1[];
    uint32_t sbase = smem_u32(sm1);

    int tid = threadIdx.x, lane = tid & 31, warp = tid >> 5;
    int wm = warp & 3, wn = warp >> 2;       // 4 x 2 warp grid
    int g = lane >> 2, tg = lane & 3;
    int l15 = lane & 15, hi = lane >> 4;

    // ---- global->smem load setup (16B chunks, 8 per 128B row); self-advancing src ----
    const __half* asrc[4]; uint32_t adst[4];
#pragma unroll
    for (int i = 0; i < 4; i++) {
        int lin = i * THREADS + tid;
        int row = lin >> 3, ch = lin & 7;
        int s = mt * BM + row;
        int tok = g_list[e * T_TOK + min(s, cnt - 1)];
        asrc[i] = g_xh + (size_t)tok * D_MODEL + ch * 8;
        adst[i] = sbase + row * 128 + ((uint32_t)(ch ^ (row & 7)) << 4);
    }
    const __half* b1src[2]; const __half* b3src[2]; uint32_t bdst[2];
#pragma unroll
    for (int i = 0; i < 2; i++) {
        int lin = i * THREADS + tid;
        int row = lin >> 3, ch = lin & 7;
        size_t off = ((size_t)e * D_MLP + nt * BN + row) * D_MODEL + ch * 8;
        b1src[i] = g_w1h + off;
        b3src[i] = g_w3h + off;
        bdst[i] = sbase + A_BYTES + row * 128 + ((uint32_t)(ch ^ (row & 7)) << 4);
    }

    // ---- ldmatrix address precompute (swizzle folded: off = (kk<<5) ^ m) ----
    uint32_t aA[2], mA[2];
#pragma unroll
    for (int tm = 0; tm < 2; tm++) {
        int r = wm * 32 + tm * 16 + l15;
        aA[tm] = sbase + r * 128;
        mA[tm] = (uint32_t)((hi ^ (r & 7)) << 4);
    }
    uint32_t aB[2], mB[2];
#pragma unroll
    for (int ns = 0; ns < 2; ns++) {
        int r = wn * 32 + ns * 16 + l15;
        aB[ns] = sbase + A_BYTES + r * 128;
        mB[ns] = (uint32_t)((hi ^ (r & 7)) << 4);
    }

    float c1[2][4][4] = {}, c3[2][4][4] = {};

    const int NK = D_MODEL / BK;  // 16

    auto fill = [&](int st) {
        uint32_t so = (uint32_t)st * STAGE1;
#pragma unroll
        for (int i = 0; i < 4; i++) { cp16(adst[i] + so, asrc[i]); asrc[i] += BK; }
#pragma unroll
        for (int i = 0; i < 2; i++) {
            cp16(bdst[i] + so, b1src[i]);
            cp16(bdst[i] + so + B_BYTES, b3src[i]);
            b1src[i] += BK;
            b3src[i] += BK;
        }
        CP_COMMIT();
    };

    fill(0);
    fill(1);

    for (int kt = 0; kt < NK; kt++) {
        if (kt < NK - 1) { CP_WAIT1(); } else { CP_WAIT0(); }
        __syncthreads();
        if (kt + 2 < NK) fill((kt + 2) % NS1);
        uint32_t so = (uint32_t)(kt % NS1) * STAGE1;
        uint32_t aAso0 = aA[0] + so, aAso1 = aA[1] + so;
        uint32_t aBso0 = aB[0] + so, aBso1 = aB[1] + so;
#pragma unroll
        for (int kk = 0; kk < 4; kk++) {
            const uint32_t kk32 = (uint32_t)kk << 5;
            uint32_t a[2][4], q1[2][4], q3[2][4];
            ldsm4(a[0], aAso0 + (kk32 ^ mA[0]));
            ldsm4(a[1], aAso1 + (kk32 ^ mA[1]));
            {
                uint32_t ad0 = aBso0 + (kk32 ^ mB[0]);
                uint32_t ad1 = aBso1 + (kk32 ^ mB[1]);
                ldsm4(q1[0], ad0);
                ldsm4(q1[1], ad1);
                ldsm4(q3[0], ad0 + B_BYTES);
                ldsm4(q3[1], ad1 + B_BYTES);
            }
#pragma unroll
            for (int tm = 0; tm < 2; tm++)
#pragma unroll
                for (int ns = 0; ns < 2; ns++) {
                    uint32_t b1a[2] = {q1[ns][0], q1[ns][2]}, b1b[2] = {q1[ns][1], q1[ns][3]};
                    uint32_t b3a[2] = {q3[ns][0], q3[ns][2]}, b3b[2] = {q3[ns][1], q3[ns][3]};
                    mma16816(c1[tm][ns * 2 + 0], a[tm], b1a);
                    mma16816(c1[tm][ns * 2 + 1], a[tm], b1b);
                    mma16816(c3[tm][ns * 2 + 0], a[tm], b3a);
                    mma16816(c3[tm][ns * 2 + 1], a[tm], b3b);
                }
        }
    }

    // epilogue: h = silu(h1) * h3 -> fp16
#pragma unroll
    for (int tm = 0; tm < 2; tm++)
#pragma unroll
        for (int pair = 0; pair < 2; pair++) {
            int s = mt * BM + wm * 32 + tm * 16 + g + pair * 8;
            if (s >= cnt) continue;
#pragma unroll
            for (int tn = 0; tn < 4; tn++) {
                float h1a = c1[tm][tn][pair * 2 + 0];
                float h1b = c1[tm][tn][pair * 2 + 1];
                float h3a = c3[tm][tn][pair * 2 + 0];
                float h3b = c3[tm][tn][pair * 2 + 1];
                float ha = h1a / (1.f + expf(-h1a)) * h3a;
                float hb = h1b / (1.f + expf(-h1b)) * h3b;
                int col = nt * BN + wn * 32 + tn * 8 + tg * 2;
                *reinterpret_cast<__half2*>(&g_h[((size_t)e * T_TOK + s) * D_MLP + col]) =
                    __floats2half2_rn(ha, hb);
            }
        }
}

// ---------------- grouped GEMM2: out += w * (H @ W2^T), fused atomic combine ----------------
// grid: (D_MODEL/BN, T_TOK/BM, EHALF), block 256, dynamic smem NS2*STAGE2
__global__ void __launch_bounds__(THREADS, 2) gemm2_kernel(float* __restrict__ out, int ebase) {
    int e = blockIdx.z + ebase, mt = blockIdx.y, nt = blockIdx.x;
    int cnt = g_cnt[e];
    if (mt * BM >= cnt) return;

    extern __shared__ __align__(128) char sm2[];
    uint32_t sbase = smem_u32(sm2);

    int tid = threadIdx.x, lane = tid & 31, warp = tid >> 5;
    int wm = warp & 3, wn = warp >> 2;
    int g = lane >> 2, tg = lane & 3;
    int l15 = lane & 15, hi = lane >> 4;

    const __half* asrc[4]; uint32_t adst[4];
#pragma unroll
    for (int i = 0; i < 4; i++) {
        int lin = i * THREADS + tid;
        int row = lin >> 3, ch = lin & 7;
        asrc[i] = g_h + ((size_t)e * T_TOK + mt * BM + row) * D_MLP + ch * 8;
        adst[i] = sbase + row * 128 + ((uint32_t)(ch ^ (row & 7)) << 4);
    }
    const __half* bsrc[2]; uint32_t bdst[2];
#pragma unroll
    for (int i = 0; i < 2; i++) {
        int lin = i * THREADS + tid;
        int row = lin >> 3, ch = lin & 7;
        bsrc[i] = g_w2h + ((size_t)e * D_MODEL + nt * BN + row) * D_MLP + ch * 8;
        bdst[i] = sbase + A_BYTES + row * 128 + ((uint32_t)(ch ^ (row & 7)) << 4);
    }

    uint32_t aA[2], mA[2];
#pragma unroll
    for (int tm = 0; tm < 2; tm++) {
        int r = wm * 32 + tm * 16 + l15;
        aA[tm] = sbase + r * 128;
        mA[tm] = (uint32_t)((hi ^ (r & 7)) << 4);
    }
    uint32_t aB[2], mB[2];
#pragma unroll
    for (int ns = 0; ns < 2; ns++) {
        int r = wn * 32 + ns * 16 + l15;
        aB[ns] = sbase + A_BYTES + r * 128;
        mB[ns] = (uint32_t)((hi ^ (r & 7)) << 4);
    }

    float c[2][4][4] = {};

    const int NK = D_MLP / BK;  // 56

    auto fill = [&](int st) {
        uint32_t so = (uint32_t)st * STAGE2;
#pragma unroll
        for (int i = 0; i < 4; i++) { cp16(adst[i] + so, asrc[i]); asrc[i] += BK; }
#pragma unroll
        for (int i = 0; i < 2; i++) { cp16(bdst[i] + so, bsrc[i]); bsrc[i] += BK; }
        CP_COMMIT();
    };

    fill(0);
    fill(1);
    fill(2);

    for (int kt = 0; kt < NK; kt++) {
        int rem = NK - 1 - kt;
        if (rem >= 2)      { CP_WAIT2(); }
        else if (rem == 1) { CP_WAIT1(); }
        else               { CP_WAIT0(); }
        __syncthreads();
        if (kt + 3 < NK) fill((kt + 3) & 3);
        uint32_t so = (uint32_t)(kt & 3) * STAGE2;
        uint32_t aAso0 = aA[0] + so, aAso1 = aA[1] + so;
        uint32_t aBso0 = aB[0] + so, aBso1 = aB[1] + so;
#pragma unroll
        for (int kk = 0; kk < 4; kk++) {
            const uint32_t kk32 = (uint32_t)kk << 5;
            uint32_t a[2][4], q[2][4];
            ldsm4(a[0], aAso0 + (kk32 ^ mA[0]));
            ldsm4(a[1], aAso1 + (kk32 ^ mA[1]));
            ldsm4(q[0], aBso0 + (kk32 ^ mB[0]));
            ldsm4(q[1], aBso1 + (kk32 ^ mB[1]));
#pragma unroll
            for (int tm = 0; tm < 2; tm++)
#pragma unroll
                for (int ns = 0; ns < 2; ns++) {
                    uint32_t ba[2] = {q[ns][0], q[ns][2]}, bb[2] = {q[ns][1], q[ns][3]};
                    mma16816(c[tm][ns * 2 + 0], a[tm], ba);
                    mma16816(c[tm][ns * 2 + 1], a[tm], bb);
                }
        }
    }

    // epilogue: weighted atomic combine directly into output (2 commutative
    // fp32 adds per element -> deterministic)
#pragma unroll
    for (int tm = 0; tm < 2; tm++)
#pragma unroll
        for (int pair = 0; pair < 2; pair++) {
            int s = mt * BM + wm * 32 + tm * 16 + g + pair * 8;
            if (s >= cnt) continue;
            int token = g_list[e * T_TOK + s];
            float w = g_wts[e * T_TOK + s];
            float* dst = out + (size_t)token * D_MODEL;
#pragma unroll
            for (int tn = 0; tn < 4; tn++) {
                int col = nt * BN + wn * 32 + tn * 8 + tg * 2;
                atomicAdd(dst + col + 0, c[tm][tn][pair * 2 + 0] * w);
                atomicAdd(dst + col + 1, c[tm][tn][pair * 2 + 1] * w);
            }
        }
}

// ---------------- stream/event resources (host objects, created once pre-capture) ----------------
struct MoeResources {
    cudaStream_t s1, s2;
    cudaEvent_t e0, eg, ecA, ec23, ecB, eg1a, e2a;
    MoeResources() {
        cudaStreamCreateWithFlags(&s1, cudaStreamNonBlocking);
        cudaStreamCreateWithFlags(&s2, cudaStreamNonBlocking);
        cudaEventCreateWithFlags(&e0, cudaEventDisableTiming);
        cudaEventCreateWithFlags(&eg, cudaEventDisableTiming);
        cudaEventCreateWithFlags(&ecA, cudaEventDisableTiming);
        cudaEventCreateWithFlags(&ec23, cudaEventDisableTiming);
        cudaEventCreateWithFlags(&ecB, cudaEventDisableTiming);
        cudaEventCreateWithFlags(&eg1a, cudaEventDisableTiming);
        cudaEventCreateWithFlags(&e2a, cudaEventDisableTiming);
        cudaFuncSetAttribute(gemm1_kernel, cudaFuncAttributeMaxDynamicSharedMemorySize, NS1 * STAGE1);
        cudaFuncSetAttribute(gemm2_kernel, cudaFuncAttributeMaxDynamicSharedMemorySize, NS2 * STAGE2);
    }
};

// ---------------- launch ----------------
extern "C" void kernel_launch(void* const* d_in, const int* in_sizes, int n_in,
                              void* d_out, int out_size) {
    const float* x = (const float*)d_in[0];
    const float* w_gate = (const float*)d_in[1];
    const float* w1 = (const float*)d_in[2];
    const float* w3 = (const float*)d_in[3];
    const float* w2 = (const float*)d_in[4];
    float* out = (float*)d_out;

    static MoeResources res;  // constructed on first (non-captured) call

    // fork point on the main (captured) stream
    cudaEventRecord(res.e0, 0);

    // s1: zero output + counters -> gating (+ x fp16 conversion)
    cudaStreamWaitEvent(res.s1, res.e0, 0);
    zero_kernel<<<1024, 256, 0, res.s1>>>((float4*)out, (T_TOK * D_MODEL) / 4);
    gate_kernel<<<T_TOK / 4, 128, 0, res.s1>>>(x, w_gate);
    cudaEventRecord(res.eg, res.s1);

    // main: convert W1/W3 for experts 0-1 only (minimal critical path)
    dim3 gcq(512, 2);
    cvt_w13_kernel<<<gcq, 256>>>(w1, w3, 0, EQTR);
    cudaEventRecord(res.ecA, 0);

    // s2: cvt e2-3 (concurrent with gemm1 q0), cvt e4-7 (concurrent with gemm1 q1),
    //     then W2 (concurrent with gemm1b)
    cudaStreamWaitEvent(res.s2, res.ecA, 0);
    cvt_w13_kernel<<<gcq, 256, 0, res.s2>>>(w1, w3, EQTR, EQTR);
    cudaEventRecord(res.ec23, res.s2);
    dim3 gch(1024, 2);
    cvt_w13_kernel<<<gch, 256, 0, res.s2>>>(w1, w3, EHALF, EHALF);
    cudaEventRecord(res.ecB, res.s2);
    cvt_w2_kernel<<<2048, 256, 0, res.s2>>>(w2);

    // main: gemm1 q0 (experts 0-1) after gate; weights e0-1 ready via stream order
    cudaStreamWaitEvent(0, res.eg, 0);
    dim3 g1q(D_MLP / BN, T_TOK / BM, EQTR);
    gemm1_kernel<<<g1q, THREADS, NS1 * STAGE1>>>(0);

    // main: gemm1 q1 (experts 2-3) after its weight chunk
    cudaStreamWaitEvent(0, res.ec23, 0);
    gemm1_kernel<<<g1q, THREADS, NS1 * STAGE1>>>(EQTR);
    cudaEventRecord(res.eg1a, 0);

    // s2: gemm2a (experts 0-3) — waits gemm1(e0-3) (event) + W2 cvt (stream order);
    // runs concurrent with gemm1b, filling its tail waves
    cudaStreamWaitEvent(res.s2, res.eg1a, 0);
    dim3 g2(D_MODEL / BN, T_TOK / BM, EHALF);
    gemm2_kernel<<<g2, THREADS, NS2 * STAGE2, res.s2>>>(out, 0);
    cudaEventRecord(res.e2a, res.s2);

    // main: gemm1b (experts 4-7) after its weight chunk
    cudaStreamWaitEvent(0, res.ecB, 0);
    dim3 g1h(D_MLP / BN, T_TOK / BM, EHALF);
    gemm1_kernel<<<g1h, THREADS, NS1 * STAGE1>>>(EHALF);

    // main: gemm2b (experts 4-7) after gemm1b (stream order) + s2 branch join
    cudaStreamWaitEvent(0, res.e2a, 0);
    gemm2_kernel<<<g2, THREADS, NS2 * STAGE2>>>(out, EHALF);
}

// round 16
// speedup vs baseline: 1.2005x; 1.0256x over previous
#include <cuda_runtime.h>
#include <cuda_fp16.h>
#include <cstdint>
#include <math.h>

// Problem constants
#define T_TOK 4096
#define D_MODEL 1024
#define D_MLP 3584
#define NEXP 8
#define EHALF 4

// GEMM tile config
#define BM 128
#define BN 64
#define BK 64
#define THREADS 256
#define NS1 3            // gemm1 pipeline stages
#define NS2 4            // gemm2 pipeline stages

// smem stage sizes (bytes)
#define A_BYTES (BM * BK * 2)             // 16384
#define B_BYTES (BN * BK * 2)             // 8192
#define STAGE1 (A_BYTES + 2 * B_BYTES)    // 32768 (gemm1: A + B1 + B3)
#define STAGE2 (A_BYTES + B_BYTES)        // 24576 (gemm2: A + B)

// ---------------- device scratch (static: no cudaMalloc allowed) ----------------
static __device__ __align__(16) __half g_xh[T_TOK * D_MODEL];
static __device__ __align__(16) __half g_w1h[NEXP * D_MLP * D_MODEL];
static __device__ __align__(16) __half g_w3h[NEXP * D_MLP * D_MODEL];
static __device__ __align__(16) __half g_w2h[NEXP * D_MODEL * D_MLP];
static __device__ __align__(16) __half g_h[(size_t)NEXP * T_TOK * D_MLP];
static __device__ int    g_cnt[NEXP];
static __device__ int    g_list[NEXP * T_TOK];
static __device__ float  g_wts[NEXP * T_TOK];

// ---------------- helpers ----------------
__device__ __forceinline__ void mma16816(float* c, const uint32_t* a, const uint32_t* b) {
    asm volatile(
        "mma.sync.aligned.m16n8k16.row.col.f32.f16.f16.f32 "
        "{%0,%1,%2,%3}, {%4,%5,%6,%7}, {%8,%9}, {%0,%1,%2,%3};"
        : "+f"(c[0]), "+f"(c[1]), "+f"(c[2]), "+f"(c[3])
        : "r"(a[0]), "r"(a[1]), "r"(a[2]), "r"(a[3]), "r"(b[0]), "r"(b[1]));
}

__device__ __forceinline__ void ldsm4(uint32_t* r, uint32_t saddr) {
    asm volatile("ldmatrix.sync.aligned.m8n8.x4.shared.b16 {%0,%1,%2,%3}, [%4];"
                 : "=r"(r[0]), "=r"(r[1]), "=r"(r[2]), "=r"(r[3]) : "r"(saddr));
}

__device__ __forceinline__ void cp16(uint32_t dst, const void* src) {
    asm volatile("cp.async.cg.shared.global [%0], [%1], 16;" :: "r"(dst), "l"(src));
}
#define CP_COMMIT() asm volatile("cp.async.commit_group;")
#define CP_WAIT2()  asm volatile("cp.async.wait_group 2;")
#define CP_WAIT1()  asm volatile("cp.async.wait_group 1;")
#define CP_WAIT0()  asm volatile("cp.async.wait_group 0;")

__device__ __forceinline__ uint32_t smem_u32(const void* p) {
    return (uint32_t)__cvta_generic_to_shared(p);
}

// ---------------- kernel 0: zero output + counters ----------------
__global__ void zero_kernel(float4* out4, int n4) {
    int i = blockIdx.x * blockDim.x + threadIdx.x;
    float4 z = make_float4(0.f, 0.f, 0.f, 0.f);
    for (; i < n4; i += gridDim.x * blockDim.x) out4[i] = z;
    if (blockIdx.x == 0 && threadIdx.x < NEXP) g_cnt[threadIdx.x] = 0;
}

// ---------------- W1/W3 fp32 -> fp16, per-expert-half chunks ----------------
// grid: (1024, 2); blockIdx.y: 0 -> W1, 1 -> W3. ebase: first expert of chunk.
__global__ void cvt_w13_kernel(const float* __restrict__ w1,
                               const float* __restrict__ w3, int ebase) {
    const int n4 = (EHALF * D_MLP * D_MODEL) / 4;   // this chunk's float4 count
    const size_t base4 = (size_t)ebase * (D_MLP * D_MODEL / 4);
    const float* src = (blockIdx.y == 0) ? w1 : w3;
    __half* dst = (blockIdx.y == 0) ? g_w1h : g_w3h;
    const float4* s4 = reinterpret_cast<const float4*>(src) + base4;
    __half2* d2 = reinterpret_cast<__half2*>(dst) + 2 * base4;
    int i = blockIdx.x * blockDim.x + threadIdx.x;
    for (; i < n4; i += gridDim.x * blockDim.x) {
        float4 v = s4[i];
        d2[2 * i + 0] = __floats2half2_rn(v.x, v.y);
        d2[2 * i + 1] = __floats2half2_rn(v.z, v.w);
    }
}

__global__ void cvt_w2_kernel(const float* __restrict__ w2) {
    const int n4 = (NEXP * D_MLP * D_MODEL) / 4;
    const float4* s4 = reinterpret_cast<const float4*>(w2);
    __half2* d2 = reinterpret_cast<__half2*>(g_w2h);
    int i = blockIdx.x * blockDim.x + threadIdx.x;
    for (; i < n4; i += gridDim.x * blockDim.x) {
        float4 v = s4[i];
        d2[2 * i + 0] = __floats2half2_rn(v.x, v.y);
        d2[2 * i + 1] = __floats2half2_rn(v.z, v.w);
    }
}

// ---------------- gating (warp per token) + x->fp16 ----------------
__global__ void gate_kernel(const float* __restrict__ x, const float* __restrict__ wg) {
    int t = blockIdx.x * 4 + (threadIdx.x >> 5);
    int lane = threadIdx.x & 31;
    if (t >= T_TOK) return;
    const float* xr = x + (size_t)t * D_MODEL;
    float acc[NEXP];
#pragma unroll
    for (int e = 0; e < NEXP; e++) acc[e] = 0.f;
    for (int d = lane; d < D_MODEL; d += 32) {
        float xv = xr[d];
        g_xh[(size_t)t * D_MODEL + d] = __float2half_rn(xv);
#pragma unroll
        for (int e = 0; e < NEXP; e++) acc[e] += xv * wg[e * D_MODEL + d];
    }
#pragma unroll
    for (int e = 0; e < NEXP; e++)
#pragma unroll
        for (int o = 16; o; o >>= 1) acc[e] += __shfl_xor_sync(0xFFFFFFFFu, acc[e], o);
    if (lane == 0) {
        int i0 = 0;
        float l0 = acc[0];
#pragma unroll
        for (int e = 1; e < NEXP; e++)
            if (acc[e] > l0) { l0 = acc[e]; i0 = e; }
        int i1 = -1;
        float l1 = -INFINITY;
#pragma unroll
        for (int e = 0; e < NEXP; e++)
            if (e != i0 && acc[e] > l1) { l1 = acc[e]; i1 = e; }
        float e1 = expf(l1 - l0);
        float s = 1.f + e1;
        float w0 = 1.f / s, w1 = e1 / s;
        int p0 = atomicAdd(&g_cnt[i0], 1);
        g_list[i0 * T_TOK + p0] = t;
        g_wts[i0 * T_TOK + p0] = w0;
        int p1 = atomicAdd(&g_cnt[i1], 1);
        g_list[i1 * T_TOK + p1] = t;
        g_wts[i1 * T_TOK + p1] = w1;
    }
}

// ---------------- grouped GEMM1: h = silu(X@W1^T) * (X@W3^T), fp16 out ----------------
// grid: (D_MLP/BN, T_TOK/BM, EHALF), block 256, dynamic smem NS1*STAGE1
__global__ void __launch_bounds__(THREADS, 2) gemm1_kernel(int ebase) {
    int e = blockIdx.z + ebase, mt = blockIdx.y, nt = blockIdx.x;
    int cnt = g_cnt[e];
    if (mt * BM >= cnt) return;

    extern __shared__ __align__(128) char sm1[];
    uint32_t sbase = smem_u32(sm1);

    int tid = threadIdx.x, lane = tid & 31, warp = tid >> 5;
    int wm = warp & 3, wn = warp >> 2;       // 4 x 2 warp grid
    int g = lane >> 2, tg = lane & 3;
    int l15 = lane & 15, hi = lane >> 4;

    // ---- global->smem load setup (16B chunks, 8 per 128B row); self-advancing src ----
    const __half* asrc[4]; uint32_t adst[4];
#pragma unroll
    for (int i = 0; i < 4; i++) {
        int lin = i * THREADS + tid;
        int row = lin >> 3, ch = lin & 7;
        int s = mt * BM + row;
        int tok = g_list[e * T_TOK + min(s, cnt - 1)];
        asrc[i] = g_xh + (size_t)tok * D_MODEL + ch * 8;
        adst[i] = sbase + row * 128 + ((uint32_t)(ch ^ (row & 7)) << 4);
    }
    const __half* b1src[2]; const __half* b3src[2]; uint32_t bdst[2];
#pragma unroll
    for (int i = 0; i < 2; i++) {
        int lin = i * THREADS + tid;
        int row = lin >> 3, ch = lin & 7;
        size_t off = ((size_t)e * D_MLP + nt * BN + row) * D_MODEL + ch * 8;
        b1src[i] = g_w1h + off;
        b3src[i] = g_w3h + off;
        bdst[i] = sbase + A_BYTES + row * 128 + ((uint32_t)(ch ^ (row & 7)) << 4);
    }

    // ---- ldmatrix address precompute (swizzle folded: off = (kk<<5) ^ m) ----
    uint32_t aA[2], mA[2];
#pragma unroll
    for (int tm = 0; tm < 2; tm++) {
        int r = wm * 32 + tm * 16 + l15;
        aA[tm] = sbase + r * 128;
        mA[tm] = (uint32_t)((hi ^ (r & 7)) << 4);
    }
    uint32_t aB[2], mB[2];
#pragma unroll
    for (int ns = 0; ns < 2; ns++) {
        int r = wn * 32 + ns * 16 + l15;
        aB[ns] = sbase + A_BYTES + r * 128;
        mB[ns] = (uint32_t)((hi ^ (r & 7)) << 4);
    }

    float c1[2][4][4] = {}, c3[2][4][4] = {};

    const int NK = D_MODEL / BK;  // 16

    auto fill = [&](int st) {
        uint32_t so = (uint32_t)st * STAGE1;
#pragma unroll
        for (int i = 0; i < 4; i++) { cp16(adst[i] + so, asrc[i]); asrc[i] += BK; }
#pragma unroll
        for (int i = 0; i < 2; i++) {
            cp16(bdst[i] + so, b1src[i]);
            cp16(bdst[i] + so + B_BYTES, b3src[i]);
            b1src[i] += BK;
            b3src[i] += BK;
        }
        CP_COMMIT();
    };

    fill(0);
    fill(1);

    for (int kt = 0; kt < NK; kt++) {
        if (kt < NK - 1) { CP_WAIT1(); } else { CP_WAIT0(); }
        __syncthreads();
        if (kt + 2 < NK) fill((kt + 2) % NS1);
        uint32_t so = (uint32_t)(kt % NS1) * STAGE1;
        uint32_t aAso0 = aA[0] + so, aAso1 = aA[1] + so;
        uint32_t aBso0 = aB[0] + so, aBso1 = aB[1] + so;
#pragma unroll
        for (int kk = 0; kk < 4; kk++) {
            const uint32_t kk32 = (uint32_t)kk << 5;
            uint32_t a[2][4], q1[2][4], q3[2][4];
            ldsm4(a[0], aAso0 + (kk32 ^ mA[0]));
            ldsm4(a[1], aAso1 + (kk32 ^ mA[1]));
            {
                uint32_t ad0 = aBso0 + (kk32 ^ mB[0]);
                uint32_t ad1 = aBso1 + (kk32 ^ mB[1]);
                ldsm4(q1[0], ad0);
                ldsm4(q1[1], ad1);
                ldsm4(q3[0], ad0 + B_BYTES);
                ldsm4(q3[1], ad1 + B_BYTES);
            }
#pragma unroll
            for (int tm = 0; tm < 2; tm++)
#pragma unroll
                for (int ns = 0; ns < 2; ns++) {
                    uint32_t b1a[2] = {q1[ns][0], q1[ns][2]}, b1b[2] = {q1[ns][1], q1[ns][3]};
                    uint32_t b3a[2] = {q3[ns][0], q3[ns][2]}, b3b[2] = {q3[ns][1], q3[ns][3]};
                    mma16816(c1[tm][ns * 2 + 0], a[tm], b1a);
                    mma16816(c1[tm][ns * 2 + 1], a[tm], b1b);
                    mma16816(c3[tm][ns * 2 + 0], a[tm], b3a);
                    mma16816(c3[tm][ns * 2 + 1], a[tm], b3b);
                }
        }
    }

    // epilogue: h = silu(h1) * h3 -> fp16
#pragma unroll
    for (int tm = 0; tm < 2; tm++)
#pragma unroll
        for (int pair = 0; pair < 2; pair++) {
            int s = mt * BM + wm * 32 + tm * 16 + g + pair * 8;
            if (s >= cnt) continue;
#pragma unroll
            for (int tn = 0; tn < 4; tn++) {
                float h1a = c1[tm][tn][pair * 2 + 0];
                float h1b = c1[tm][tn][pair * 2 + 1];
                float h3a = c3[tm][tn][pair * 2 + 0];
                float h3b = c3[tm][tn][pair * 2 + 1];
                float ha = h1a / (1.f + expf(-h1a)) * h3a;
                float hb = h1b / (1.f + expf(-h1b)) * h3b;
                int col = nt * BN + wn * 32 + tn * 8 + tg * 2;
                *reinterpret_cast<__half2*>(&g_h[((size_t)e * T_TOK + s) * D_MLP + col]) =
                    __floats2half2_rn(ha, hb);
            }
        }
}

// ---------------- grouped GEMM2: out += w * (H @ W2^T), fused atomic combine ----------------
// grid: (D_MODEL/BN, T_TOK/BM, EHALF), block 256, dynamic smem NS2*STAGE2
__global__ void __launch_bounds__(THREADS, 2) gemm2_kernel(float* __restrict__ out, int ebase) {
    int e = blockIdx.z + ebase, mt = blockIdx.y, nt = blockIdx.x;
    int cnt = g_cnt[e];
    if (mt * BM >= cnt) return;

    extern __shared__ __align__(128) char sm2[];
    uint32_t sbase = smem_u32(sm2);

    int tid = threadIdx.x, lane = tid & 31, warp = tid >> 5;
    int wm = warp & 3, wn = warp >> 2;
    int g = lane >> 2, tg = lane & 3;
    int l15 = lane & 15, hi = lane >> 4;

    const __half* asrc[4]; uint32_t adst[4];
#pragma unroll
    for (int i = 0; i < 4; i++) {
        int lin = i * THREADS + tid;
        int row = lin >> 3, ch = lin & 7;
        asrc[i] = g_h + ((size_t)e * T_TOK + mt * BM + row) * D_MLP + ch * 8;
        adst[i] = sbase + row * 128 + ((uint32_t)(ch ^ (row & 7)) << 4);
    }
    const __half* bsrc[2]; uint32_t bdst[2];
#pragma unroll
    for (int i = 0; i < 2; i++) {
        int lin = i * THREADS + tid;
        int row = lin >> 3, ch = lin & 7;
        bsrc[i] = g_w2h + ((size_t)e * D_MODEL + nt * BN + row) * D_MLP + ch * 8;
        bdst[i] = sbase + A_BYTES + row * 128 + ((uint32_t)(ch ^ (row & 7)) << 4);
    }

    uint32_t aA[2], mA[2];
#pragma unroll
    for (int tm = 0; tm < 2; tm++) {
        int r = wm * 32 + tm * 16 + l15;
        aA[tm] = sbase + r * 128;
        mA[tm] = (uint32_t)((hi ^ (r & 7)) << 4);
    }
    uint32_t aB[2], mB[2];
#pragma unroll
    for (int ns = 0; ns < 2; ns++) {
        int r = wn * 32 + ns * 16 + l15;
        aB[ns] = sbase + A_BYTES + r * 128;
        mB[ns] = (uint32_t)((hi ^ (r & 7)) << 4);
    }

    float c[2][4][4] = {};

    const int NK = D_MLP / BK;  // 56

    auto fill = [&](int st) {
        uint32_t so = (uint32_t)st * STAGE2;
#pragma unroll
        for (int i = 0; i < 4; i++) { cp16(adst[i] + so, asrc[i]); asrc[i] += BK; }
#pragma unroll
        for (int i = 0; i < 2; i++) { cp16(bdst[i] + so, bsrc[i]); bsrc[i] += BK; }
        CP_COMMIT();
    };

    fill(0);
    fill(1);
    fill(2);

    for (int kt = 0; kt < NK; kt++) {
        int rem = NK - 1 - kt;
        if (rem >= 2)      { CP_WAIT2(); }
        else if (rem == 1) { CP_WAIT1(); }
        else               { CP_WAIT0(); }
        __syncthreads();
        if (kt + 3 < NK) fill((kt + 3) & 3);
        uint32_t so = (uint32_t)(kt & 3) * STAGE2;
        uint32_t aAso0 = aA[0] + so, aAso1 = aA[1] + so;
        uint32_t aBso0 = aB[0] + so, aBso1 = aB[1] + so;
#pragma unroll
        for (int kk = 0; kk < 4; kk++) {
            const uint32_t kk32 = (uint32_t)kk << 5;
            uint32_t a[2][4], q[2][4];
            ldsm4(a[0], aAso0 + (kk32 ^ mA[0]));
            ldsm4(a[1], aAso1 + (kk32 ^ mA[1]));
            ldsm4(q[0], aBso0 + (kk32 ^ mB[0]));
            ldsm4(q[1], aBso1 + (kk32 ^ mB[1]));
#pragma unroll
            for (int tm = 0; tm < 2; tm++)
#pragma unroll
                for (int ns = 0; ns < 2; ns++) {
                    uint32_t ba[2] = {q[ns][0], q[ns][2]}, bb[2] = {q[ns][1], q[ns][3]};
                    mma16816(c[tm][ns * 2 + 0], a[tm], ba);
                    mma16816(c[tm][ns * 2 + 1], a[tm], bb);
                }
        }
    }

    // epilogue: weighted atomic combine directly into output (2 commutative
    // fp32 adds per element -> deterministic)
#pragma unroll
    for (int tm = 0; tm < 2; tm++)
#pragma unroll
        for (int pair = 0; pair < 2; pair++) {
            int s = mt * BM + wm * 32 + tm * 16 + g + pair * 8;
            if (s >= cnt) continue;
            int token = g_list[e * T_TOK + s];
            float w = g_wts[e * T_TOK + s];
            float* dst = out + (size_t)token * D_MODEL;
#pragma unroll
            for (int tn = 0; tn < 4; tn++) {
                int col = nt * BN + wn * 32 + tn * 8 + tg * 2;
                atomicAdd(dst + col + 0, c[tm][tn][pair * 2 + 0] * w);
                atomicAdd(dst + col + 1, c[tm][tn][pair * 2 + 1] * w);
            }
        }
}

// ---------------- stream/event resources (host objects, created once pre-capture) ----------------
struct MoeResources {
    cudaStream_t s1, s2;
    cudaEvent_t e0, eg, ecA, ecB, ew2, eg1a, e2a;
    MoeResources() {
        cudaStreamCreateWithFlags(&s1, cudaStreamNonBlocking);
        cudaStreamCreateWithFlags(&s2, cudaStreamNonBlocking);
        cudaEventCreateWithFlags(&e0, cudaEventDisableTiming);
        cudaEventCreateWithFlags(&eg, cudaEventDisableTiming);
        cudaEventCreateWithFlags(&ecA, cudaEventDisableTiming);
        cudaEventCreateWithFlags(&ecB, cudaEventDisableTiming);
        cudaEventCreateWithFlags(&ew2, cudaEventDisableTiming);
        cudaEventCreateWithFlags(&eg1a, cudaEventDisableTiming);
        cudaEventCreateWithFlags(&e2a, cudaEventDisableTiming);
        cudaFuncSetAttribute(gemm1_kernel, cudaFuncAttributeMaxDynamicSharedMemorySize, NS1 * STAGE1);
        cudaFuncSetAttribute(gemm2_kernel, cudaFuncAttributeMaxDynamicSharedMemorySize, NS2 * STAGE2);
    }
};

// ---------------- launch ----------------
extern "C" void kernel_launch(void* const* d_in, const int* in_sizes, int n_in,
                              void* d_out, int out_size) {
    const float* x = (const float*)d_in[0];
    const float* w_gate = (const float*)d_in[1];
    const float* w1 = (const float*)d_in[2];
    const float* w3 = (const float*)d_in[3];
    const float* w2 = (const float*)d_in[4];
    float* out = (float*)d_out;

    static MoeResources res;  // constructed on first (non-captured) call

    // fork point on the main (captured) stream
    cudaEventRecord(res.e0, 0);

    // s1: zero output + counters -> gating (+ x fp16 conversion)
    cudaStreamWaitEvent(res.s1, res.e0, 0);
    zero_kernel<<<1024, 256, 0, res.s1>>>((float4*)out, (T_TOK * D_MODEL) / 4);
    gate_kernel<<<T_TOK / 4, 128, 0, res.s1>>>(x, w_gate);
    cudaEventRecord(res.eg, res.s1);

    // main: convert W1/W3 for experts 0-3 only (the gemm1a critical path)
    dim3 gcvt(1024, 2);
    cvt_w13_kernel<<<gcvt, 256>>>(w1, w3, 0);
    cudaEventRecord(res.ecA, 0);

    // s2: convert W1/W3 experts 4-7 (concurrent with gemm1a), then W2
    cudaStreamWaitEvent(res.s2, res.ecA, 0);
    cvt_w13_kernel<<<gcvt, 256, 0, res.s2>>>(w1, w3, EHALF);
    cudaEventRecord(res.ecB, res.s2);
    cvt_w2_kernel<<<2048, 256, 0, res.s2>>>(w2);
    cudaEventRecord(res.ew2, res.s2);

    // main: gemm1a (experts 0-3) after gate; weights e0-3 ready via stream order
    cudaStreamWaitEvent(0, res.eg, 0);
    dim3 g1(D_MLP / BN, T_TOK / BM, EHALF);
    gemm1_kernel<<<g1, THREADS, NS1 * STAGE1>>>(0);
    cudaEventRecord(res.eg1a, 0);

    // s2: gemm2a (experts 0-3) — waits gemm1a (event) + W2 cvt (stream order);
    // runs concurrent with gemm1b, filling its tail waves
    cudaStreamWaitEvent(res.s2, res.eg1a, 0);
    dim3 g2(D_MODEL / BN, T_TOK / BM, EHALF);
    gemm2_kernel<<<g2, THREADS, NS2 * STAGE2, res.s2>>>(out, 0);
    cudaEventRecord(res.e2a, res.s2);

    // main: gemm1b (experts 4-7) after its weight chunk
    cudaStreamWaitEvent(0, res.ecB, 0);
    gemm1_kernel<<<g1, THREADS, NS1 * STAGE1>>>(EHALF);

    // main: gemm2b (experts 4-7) — needs only gemm1b (stream order) + W2 (ew2);
    // may overlap gemm2a's tail (atomic combine is order-independent bitwise)
    cudaStreamWaitEvent(0, res.ew2, 0);
    gemm2_kernel<<<g2, THREADS, NS2 * STAGE2>>>(out, EHALF);

    // join the s2 branch into the captured main stream (after gemm2b launch,
    // so it does NOT serialize gemm2b behind gemm2a)
    cudaStreamWaitEvent(0, res.e2a, 0);
}

// round 17
// speedup vs baseline: 1.2031x; 1.0022x over previous
#include <cuda_runtime.h>
#include <cuda_fp16.h>
#include <cstdint>
#include <math.h>

// Problem constants
#define T_TOK 4096
#define D_MODEL 1024
#define D_MLP 3584
#define NEXP 8
#define EHALF 4

// GEMM tile config
#define BM 128
#define BN 64
#define BK 64
#define THREADS 256
#define NS1 3            // gemm1 pipeline stages
#define NS2 4            // gemm2 pipeline stages

// smem stage sizes (bytes)
#define A_BYTES (BM * BK * 2)             // 16384
#define B_BYTES (BN * BK * 2)             // 8192
#define STAGE1 (A_BYTES + 2 * B_BYTES)    // 32768 (gemm1: A + B1 + B3)
#define STAGE2 (A_BYTES + B_BYTES)        // 24576 (gemm2: A + B)

// ---------------- device scratch (static: no cudaMalloc allowed) ----------------
static __device__ __align__(16) __half g_xh[T_TOK * D_MODEL];
static __device__ __align__(16) __half g_w1h[NEXP * D_MLP * D_MODEL];
static __device__ __align__(16) __half g_w3h[NEXP * D_MLP * D_MODEL];
static __device__ __align__(16) __half g_w2h[NEXP * D_MODEL * D_MLP];
static __device__ __align__(16) __half g_h[(size_t)NEXP * T_TOK * D_MLP];
static __device__ int    g_cnt[NEXP];
static __device__ int    g_list[NEXP * T_TOK];
static __device__ float  g_wts[NEXP * T_TOK];

// ---------------- helpers ----------------
__device__ __forceinline__ void mma16816(float* c, const uint32_t* a, const uint32_t* b) {
    asm volatile(
        "mma.sync.aligned.m16n8k16.row.col.f32.f16.f16.f32 "
        "{%0,%1,%2,%3}, {%4,%5,%6,%7}, {%8,%9}, {%0,%1,%2,%3};"
        : "+f"(c[0]), "+f"(c[1]), "+f"(c[2]), "+f"(c[3])
        : "r"(a[0]), "r"(a[1]), "r"(a[2]), "r"(a[3]), "r"(b[0]), "r"(b[1]));
}

__device__ __forceinline__ void ldsm4(uint32_t* r, uint32_t saddr) {
    asm volatile("ldmatrix.sync.aligned.m8n8.x4.shared.b16 {%0,%1,%2,%3}, [%4];"
                 : "=r"(r[0]), "=r"(r[1]), "=r"(r[2]), "=r"(r[3]) : "r"(saddr));
}

__device__ __forceinline__ void cp16(uint32_t dst, const void* src) {
    asm volatile("cp.async.cg.shared.global [%0], [%1], 16;" :: "r"(dst), "l"(src));
}
#define CP_COMMIT() asm volatile("cp.async.commit_group;")
#define CP_WAIT2()  asm volatile("cp.async.wait_group 2;")
#define CP_WAIT1()  asm volatile("cp.async.wait_group 1;")
#define CP_WAIT0()  asm volatile("cp.async.wait_group 0;")

__device__ __forceinline__ uint32_t smem_u32(const void* p) {
    return (uint32_t)__cvta_generic_to_shared(p);
}

// ---------------- kernel 0: zero output + counters ----------------
__global__ void zero_kernel(float4* out4, int n4) {
    int i = blockIdx.x * blockDim.x + threadIdx.x;
    float4 z = make_float4(0.f, 0.f, 0.f, 0.f);
    for (; i < n4; i += gridDim.x * blockDim.x) out4[i] = z;
    if (blockIdx.x == 0 && threadIdx.x < NEXP) g_cnt[threadIdx.x] = 0;
}

// ---------------- W1/W3 fp32 -> fp16, per-expert-half chunks ----------------
// grid: (1024, 2); blockIdx.y: 0 -> W1, 1 -> W3. ebase: first expert of chunk.
__global__ void cvt_w13_kernel(const float* __restrict__ w1,
                               const float* __restrict__ w3, int ebase) {
    const int n4 = (EHALF * D_MLP * D_MODEL) / 4;   // this chunk's float4 count
    const size_t base4 = (size_t)ebase * (D_MLP * D_MODEL / 4);
    const float* src = (blockIdx.y == 0) ? w1 : w3;
    __half* dst = (blockIdx.y == 0) ? g_w1h : g_w3h;
    const float4* s4 = reinterpret_cast<const float4*>(src) + base4;
    __half2* d2 = reinterpret_cast<__half2*>(dst) + 2 * base4;
    int i = blockIdx.x * blockDim.x + threadIdx.x;
    for (; i < n4; i += gridDim.x * blockDim.x) {
        float4 v = s4[i];
        d2[2 * i + 0] = __floats2half2_rn(v.x, v.y);
        d2[2 * i + 1] = __floats2half2_rn(v.z, v.w);
    }
}

__global__ void cvt_w2_kernel(const float* __restrict__ w2) {
    const int n4 = (NEXP * D_MLP * D_MODEL) / 4;
    const float4* s4 = reinterpret_cast<const float4*>(w2);
    __half2* d2 = reinterpret_cast<__half2*>(g_w2h);
    int i = blockIdx.x * blockDim.x + threadIdx.x;
    for (; i < n4; i += gridDim.x * blockDim.x) {
        float4 v = s4[i];
        d2[2 * i + 0] = __floats2half2_rn(v.x, v.y);
        d2[2 * i + 1] = __floats2half2_rn(v.z, v.w);
    }
}

// ---------------- gating (warp per token) + x->fp16 ----------------
__global__ void gate_kernel(const float* __restrict__ x, const float* __restrict__ wg) {
    int t = blockIdx.x * 4 + (threadIdx.x >> 5);
    int lane = threadIdx.x & 31;
    if (t >= T_TOK) return;
    const float* xr = x + (size_t)t * D_MODEL;
    float acc[NEXP];
#pragma unroll
    for (int e = 0; e < NEXP; e++) acc[e] = 0.f;
    for (int d = lane; d < D_MODEL; d += 32) {
        float xv = xr[d];
        g_xh[(size_t)t * D_MODEL + d] = __float2half_rn(xv);
#pragma unroll
        for (int e = 0; e < NEXP; e++) acc[e] += xv * wg[e * D_MODEL + d];
    }
#pragma unroll
    for (int e = 0; e < NEXP; e++)
#pragma unroll
        for (int o = 16; o; o >>= 1) acc[e] += __shfl_xor_sync(0xFFFFFFFFu, acc[e], o);
    if (lane == 0) {
        int i0 = 0;
        float l0 = acc[0];
#pragma unroll
        for (int e = 1; e < NEXP; e++)
            if (acc[e] > l0) { l0 = acc[e]; i0 = e; }
        int i1 = -1;
        float l1 = -INFINITY;
#pragma unroll
        for (int e = 0; e < NEXP; e++)
            if (e != i0 && acc[e] > l1) { l1 = acc[e]; i1 = e; }
        float e1 = expf(l1 - l0);
        float s = 1.f + e1;
        float w0 = 1.f / s, w1 = e1 / s;
        int p0 = atomicAdd(&g_cnt[i0], 1);
        g_list[i0 * T_TOK + p0] = t;
        g_wts[i0 * T_TOK + p0] = w0;
        int p1 = atomicAdd(&g_cnt[i1], 1);
        g_list[i1 * T_TOK + p1] = t;
        g_wts[i1 * T_TOK + p1] = w1;
    }
}

// ---------------- grouped GEMM1: h = silu(X@W1^T) * (X@W3^T), fp16 out ----------------
// grid: (D_MLP/BN, T_TOK/BM, EHALF), block 256, dynamic smem NS1*STAGE1
__global__ void __launch_bounds__(THREADS, 2) gemm1_kernel(int ebase) {
    int e = blockIdx.z + ebase, mt = blockIdx.y, nt = blockIdx.x;
    int cnt = g_cnt[e];
    if (mt * BM >= cnt) return;

    extern __shared__ __align__(128) char sm1[];
    uint32_t sbase = smem_u32(sm1);

    int tid = threadIdx.x, lane = tid & 31, warp = tid >> 5;
    int wm = warp & 3, wn = warp >> 2;       // 4 x 2 warp grid
    int g = lane >> 2, tg = lane & 3;
    int l15 = lane & 15, hi = lane >> 4;

    // ---- global->smem load setup (16B chunks, 8 per 128B row); self-advancing src ----
    const __half* asrc[4]; uint32_t adst[4];
#pragma unroll
    for (int i = 0; i < 4; i++) {
        int lin = i * THREADS + tid;
        int row = lin >> 3, ch = lin & 7;
        int s = mt * BM + row;
        int tok = g_list[e * T_TOK + min(s, cnt - 1)];
        asrc[i] = g_xh + (size_t)tok * D_MODEL + ch * 8;
        adst[i] = sbase + row * 128 + ((uint32_t)(ch ^ (row & 7)) << 4);
    }
    const __half* b1src[2]; const __half* b3src[2]; uint32_t bdst[2];
#pragma unroll
    for (int i = 0; i < 2; i++) {
        int lin = i * THREADS + tid;
        int row = lin >> 3, ch = lin & 7;
        size_t off = ((size_t)e * D_MLP + nt * BN + row) * D_MODEL + ch * 8;
        b1src[i] = g_w1h + off;
        b3src[i] = g_w3h + off;
        bdst[i] = sbase + A_BYTES + row * 128 + ((uint32_t)(ch ^ (row & 7)) << 4);
    }

    // ---- ldmatrix address precompute (swizzle folded: off = (kk<<5) ^ m) ----
    uint32_t aA[2], mA[2];
#pragma unroll
    for (int tm = 0; tm < 2; tm++) {
        int r = wm * 32 + tm * 16 + l15;
        aA[tm] = sbase + r * 128;
        mA[tm] = (uint32_t)((hi ^ (r & 7)) << 4);
    }
    uint32_t aB[2], mB[2];
#pragma unroll
    for (int ns = 0; ns < 2; ns++) {
        int r = wn * 32 + ns * 16 + l15;
        aB[ns] = sbase + A_BYTES + r * 128;
        mB[ns] = (uint32_t)((hi ^ (r & 7)) << 4);
    }

    float c1[2][4][4] = {}, c3[2][4][4] = {};

    const int NK = D_MODEL / BK;  // 16

    auto fill = [&](int st) {
        uint32_t so = (uint32_t)st * STAGE1;
#pragma unroll
        for (int i = 0; i < 4; i++) { cp16(adst[i] + so, asrc[i]); asrc[i] += BK; }
#pragma unroll
        for (int i = 0; i < 2; i++) {
            cp16(bdst[i] + so, b1src[i]);
            cp16(bdst[i] + so + B_BYTES, b3src[i]);
            b1src[i] += BK;
            b3src[i] += BK;
        }
        CP_COMMIT();
    };

    fill(0);
    fill(1);

    for (int kt = 0; kt < NK; kt++) {
        if (kt < NK - 1) { CP_WAIT1(); } else { CP_WAIT0(); }
        __syncthreads();
        if (kt + 2 < NK) fill((kt + 2) % NS1);
        uint32_t so = (uint32_t)(kt % NS1) * STAGE1;
        uint32_t aAso0 = aA[0] + so, aAso1 = aA[1] + so;
        uint32_t aBso0 = aB[0] + so, aBso1 = aB[1] + so;
#pragma unroll
        for (int kk = 0; kk < 4; kk++) {
            const uint32_t kk32 = (uint32_t)kk << 5;
            uint32_t a[2][4], q1[2][4], q3[2][4];
            ldsm4(a[0], aAso0 + (kk32 ^ mA[0]));
            ldsm4(a[1], aAso1 + (kk32 ^ mA[1]));
            {
                uint32_t ad0 = aBso0 + (kk32 ^ mB[0]);
                uint32_t ad1 = aBso1 + (kk32 ^ mB[1]);
                ldsm4(q1[0], ad0);
                ldsm4(q1[1], ad1);
                ldsm4(q3[0], ad0 + B_BYTES);
                ldsm4(q3[1], ad1 + B_BYTES);
            }
#pragma unroll
            for (int tm = 0; tm < 2; tm++)
#pragma unroll
                for (int ns = 0; ns < 2; ns++) {
                    uint32_t b1a[2] = {q1[ns][0], q1[ns][2]}, b1b[2] = {q1[ns][1], q1[ns][3]};
                    uint32_t b3a[2] = {q3[ns][0], q3[ns][2]}, b3b[2] = {q3[ns][1], q3[ns][3]};
                    mma16816(c1[tm][ns * 2 + 0], a[tm], b1a);
                    mma16816(c1[tm][ns * 2 + 1], a[tm], b1b);
                    mma16816(c3[tm][ns * 2 + 0], a[tm], b3a);
                    mma16816(c3[tm][ns * 2 + 1], a[tm], b3b);
                }
        }
    }

    // epilogue: h = silu(h1) * h3 -> fp16
#pragma unroll
    for (int tm = 0; tm < 2; tm++)
#pragma unroll
        for (int pair = 0; pair < 2; pair++) {
            int s = mt * BM + wm * 32 + tm * 16 + g + pair * 8;
            if (s >= cnt) continue;
#pragma unroll
            for (int tn = 0; tn < 4; tn++) {
                float h1a = c1[tm][tn][pair * 2 + 0];
                float h1b = c1[tm][tn][pair * 2 + 1];
                float h3a = c3[tm][tn][pair * 2 + 0];
                float h3b = c3[tm][tn][pair * 2 + 1];
                float ha = h1a / (1.f + expf(-h1a)) * h3a;
                float hb = h1b / (1.f + expf(-h1b)) * h3b;
                int col = nt * BN + wn * 32 + tn * 8 + tg * 2;
                *reinterpret_cast<__half2*>(&g_h[((size_t)e * T_TOK + s) * D_MLP + col]) =
                    __floats2half2_rn(ha, hb);
            }
        }
}

// ---------------- grouped GEMM2: out += w * (H @ W2^T), fused atomic combine ----------------
// grid: (D_MODEL/BN, T_TOK/BM, EHALF), block 256, dynamic smem NS2*STAGE2
__global__ void __launch_bounds__(THREADS, 2) gemm2_kernel(float* __restrict__ out, int ebase) {
    int e = blockIdx.z + ebase, mt = blockIdx.y, nt = blockIdx.x;
    int cnt = g_cnt[e];
    if (mt * BM >= cnt) return;

    extern __shared__ __align__(128) char sm2[];
    uint32_t sbase = smem_u32(sm2);

    int tid = threadIdx.x, lane = tid & 31, warp = tid >> 5;
    int wm = warp & 3, wn = warp >> 2;
    int g = lane >> 2, tg = lane & 3;
    int l15 = lane & 15, hi = lane >> 4;

    const __half* asrc[4]; uint32_t adst[4];
#pragma unroll
    for (int i = 0; i < 4; i++) {
        int lin = i * THREADS + tid;
        int row = lin >> 3, ch = lin & 7;
        asrc[i] = g_h + ((size_t)e * T_TOK + mt * BM + row) * D_MLP + ch * 8;
        adst[i] = sbase + row * 128 + ((uint32_t)(ch ^ (row & 7)) << 4);
    }
    const __half* bsrc[2]; uint32_t bdst[2];
#pragma unroll
    for (int i = 0; i < 2; i++) {
        int lin = i * THREADS + tid;
        int row = lin >> 3, ch = lin & 7;
        bsrc[i] = g_w2h + ((size_t)e * D_MODEL + nt * BN + row) * D_MLP + ch * 8;
        bdst[i] = sbase + A_BYTES + row * 128 + ((uint32_t)(ch ^ (row & 7)) << 4);
    }

    uint32_t aA[2], mA[2];
#pragma unroll
    for (int tm = 0; tm < 2; tm++) {
        int r = wm * 32 + tm * 16 + l15;
        aA[tm] = sbase + r * 128;
        mA[tm] = (uint32_t)((hi ^ (r & 7)) << 4);
    }
    uint32_t aB[2], mB[2];
#pragma unroll
    for (int ns = 0; ns < 2; ns++) {
        int r = wn * 32 + ns * 16 + l15;
        aB[ns] = sbase + A_BYTES + r * 128;
        mB[ns] = (uint32_t)((hi ^ (r & 7)) << 4);
    }

    float c[2][4][4] = {};

    const int NK = D_MLP / BK;  // 56

    auto fill = [&](int st) {
        uint32_t so = (uint32_t)st * STAGE2;
#pragma unroll
        for (int i = 0; i < 4; i++) { cp16(adst[i] + so, asrc[i]); asrc[i] += BK; }
#pragma unroll
        for (int i = 0; i < 2; i++) { cp16(bdst[i] + so, bsrc[i]); bsrc[i] += BK; }
        CP_COMMIT();
    };

    fill(0);
    fill(1);
    fill(2);

    for (int kt = 0; kt < NK; kt++) {
        int rem = NK - 1 - kt;
        if (rem >= 2)      { CP_WAIT2(); }
        else if (rem == 1) { CP_WAIT1(); }
        else               { CP_WAIT0(); }
        __syncthreads();
        if (kt + 3 < NK) fill((kt + 3) & 3);
        uint32_t so = (uint32_t)(kt & 3) * STAGE2;
        uint32_t aAso0 = aA[0] + so, aAso1 = aA[1] + so;
        uint32_t aBso0 = aB[0] + so, aBso1 = aB[1] + so;
#pragma unroll
        for (int kk = 0; kk < 4; kk++) {
            const uint32_t kk32 = (uint32_t)kk << 5;
            uint32_t a[2][4], q[2][4];
            ldsm4(a[0], aAso0 + (kk32 ^ mA[0]));
            ldsm4(a[1], aAso1 + (kk32 ^ mA[1]));
            ldsm4(q[0], aBso0 + (kk32 ^ mB[0]));
            ldsm4(q[1], aBso1 + (kk32 ^ mB[1]));
#pragma unroll
            for (int tm = 0; tm < 2; tm++)
#pragma unroll
                for (int ns = 0; ns < 2; ns++) {
                    uint32_t ba[2] = {q[ns][0], q[ns][2]}, bb[2] = {q[ns][1], q[ns][3]};
                    mma16816(c[tm][ns * 2 + 0], a[tm], ba);
                    mma16816(c[tm][ns * 2 + 1], a[tm], bb);
                }
        }
    }

    // epilogue: weighted atomic combine directly into output (2 commutative
    // fp32 adds per element -> deterministic)
#pragma unroll
    for (int tm = 0; tm < 2; tm++)
#pragma unroll
        for (int pair = 0; pair < 2; pair++) {
            int s = mt * BM + wm * 32 + tm * 16 + g + pair * 8;
            if (s >= cnt) continue;
            int token = g_list[e * T_TOK + s];
            float w = g_wts[e * T_TOK + s];
            float* dst = out + (size_t)token * D_MODEL;
#pragma unroll
            for (int tn = 0; tn < 4; tn++) {
                int col = nt * BN + wn * 32 + tn * 8 + tg * 2;
                atomicAdd(dst + col + 0, c[tm][tn][pair * 2 + 0] * w);
                atomicAdd(dst + col + 1, c[tm][tn][pair * 2 + 1] * w);
            }
        }
}

// ---------------- stream/event resources (host objects, created once pre-capture) ----------------
struct MoeResources {
    cudaStream_t s1, s2, s3;
    cudaEvent_t e0, eg, ecA, ecB, ew2, eg1a, eg1b, e2a;
    MoeResources() {
        cudaStreamCreateWithFlags(&s1, cudaStreamNonBlocking);
        cudaStreamCreateWithFlags(&s2, cudaStreamNonBlocking);
        cudaStreamCreateWithFlags(&s3, cudaStreamNonBlocking);
        cudaEventCreateWithFlags(&e0, cudaEventDisableTiming);
        cudaEventCreateWithFlags(&eg, cudaEventDisableTiming);
        cudaEventCreateWithFlags(&ecA, cudaEventDisableTiming);
        cudaEventCreateWithFlags(&ecB, cudaEventDisableTiming);
        cudaEventCreateWithFlags(&ew2, cudaEventDisableTiming);
        cudaEventCreateWithFlags(&eg1a, cudaEventDisableTiming);
        cudaEventCreateWithFlags(&eg1b, cudaEventDisableTiming);
        cudaEventCreateWithFlags(&e2a, cudaEventDisableTiming);
        cudaFuncSetAttribute(gemm1_kernel, cudaFuncAttributeMaxDynamicSharedMemorySize, NS1 * STAGE1);
        cudaFuncSetAttribute(gemm2_kernel, cudaFuncAttributeMaxDynamicSharedMemorySize, NS2 * STAGE2);
    }
};

// ---------------- launch ----------------
extern "C" void kernel_launch(void* const* d_in, const int* in_sizes, int n_in,
                              void* d_out, int out_size) {
    const float* x = (const float*)d_in[0];
    const float* w_gate = (const float*)d_in[1];
    const float* w1 = (const float*)d_in[2];
    const float* w3 = (const float*)d_in[3];
    const float* w2 = (const float*)d_in[4];
    float* out = (float*)d_out;

    static MoeResources res;  // constructed on first (non-captured) call

    // fork point on the main (captured) stream
    cudaEventRecord(res.e0, 0);

    // s1: zero output + counters -> gating (+ x fp16 conversion)
    cudaStreamWaitEvent(res.s1, res.e0, 0);
    zero_kernel<<<1024, 256, 0, res.s1>>>((float4*)out, (T_TOK * D_MODEL) / 4);
    gate_kernel<<<T_TOK / 4, 128, 0, res.s1>>>(x, w_gate);
    cudaEventRecord(res.eg, res.s1);

    // main: convert W1/W3 for experts 0-3 only (the gemm1a critical path)
    dim3 gcvt(1024, 2);
    cvt_w13_kernel<<<gcvt, 256>>>(w1, w3, 0);
    cudaEventRecord(res.ecA, 0);

    // s2: convert W1/W3 experts 4-7 (concurrent with gemm1a), then W2
    cudaStreamWaitEvent(res.s2, res.ecA, 0);
    cvt_w13_kernel<<<gcvt, 256, 0, res.s2>>>(w1, w3, EHALF);
    cudaEventRecord(res.ecB, res.s2);
    cvt_w2_kernel<<<2048, 256, 0, res.s2>>>(w2);
    cudaEventRecord(res.ew2, res.s2);

    // main: gemm1a (experts 0-3) after gate; weights e0-3 ready via stream order
    cudaStreamWaitEvent(0, res.eg, 0);
    dim3 g1(D_MLP / BN, T_TOK / BM, EHALF);
    gemm1_kernel<<<g1, THREADS, NS1 * STAGE1>>>(0);
    cudaEventRecord(res.eg1a, 0);

    // s3: gemm1b (experts 4-7) — runs CONCURRENT with gemm1a (fills its tail
    // waves); true deps: gate (eg) + its weight chunk (ecB)
    cudaStreamWaitEvent(res.s3, res.eg, 0);
    cudaStreamWaitEvent(res.s3, res.ecB, 0);
    gemm1_kernel<<<g1, THREADS, NS1 * STAGE1, res.s3>>>(EHALF);
    cudaEventRecord(res.eg1b, res.s3);

    // s2: gemm2a (experts 0-3) — waits gemm1a (event) + W2 cvt (stream order);
    // fills gemm1b's remaining waves / tail
    cudaStreamWaitEvent(res.s2, res.eg1a, 0);
    dim3 g2(D_MODEL / BN, T_TOK / BM, EHALF);
    gemm2_kernel<<<g2, THREADS, NS2 * STAGE2, res.s2>>>(out, 0);
    cudaEventRecord(res.e2a, res.s2);

    // main: gemm2b (experts 4-7) — waits gemm1b (eg1b) + W2 (ew2);
    // may overlap gemm2a's tail (atomic combine is order-independent bitwise)
    cudaStreamWaitEvent(0, res.eg1b, 0);
    cudaStreamWaitEvent(0, res.ew2, 0);
    gemm2_kernel<<<g2, THREADS, NS2 * STAGE2>>>(out, EHALF);

    // join the s2 branch into the captured main stream (after gemm2b launch,
    // so it does NOT serialize gemm2b behind gemm2a)
    cudaStreamWaitEvent(0, res.e2a, 0);
}